// round 14
// baseline (speedup 1.0000x reference)
#include <cuda_runtime.h>
#include <math.h>
#include <stdint.h>

#define B_ 1024
#define T_ 128
#define F_ 32
#define E_ 16
#define H_ 20
#define G_ 80      // 4*H
#define D_ 4096    // T*F
#define BT_ (B_ * T_)   // 131072

// scratch (__device__ globals; no allocations allowed)
__device__ float g_fc1[B_ * D_];                 // relu(x_flat @ fc1_w + b)
__device__ float g_zx[(size_t)E_ * BT_ * G_];    // tensor-computed L1 input proj (+b1)
__device__ float g_eo[E_ * B_];                  // per-expert outputs
__device__ float g_w[B_ * E_];                   // softmax gate weights

// ---------------- helpers -------------------------------------------------
__device__ __forceinline__ float sigmoidf_(float x) {
    float e = __expf(-x);
    float r;
    asm("rcp.approx.f32 %0, %1;" : "=f"(r) : "f"(1.0f + e));
    return r;
}
__device__ __forceinline__ uint32_t f2tf32(float x) {
    uint32_t r; asm("cvt.rna.tf32.f32 %0, %1;" : "=r"(r) : "f"(x)); return r;
}
// D += A(tf32) * B(tf32), m16n8k8
__device__ __forceinline__ void mma_tf32(float* c, const uint32_t* a, const uint32_t* b) {
    asm("mma.sync.aligned.m16n8k8.row.col.f32.tf32.tf32.f32 "
        "{%0,%1,%2,%3},{%4,%5,%6,%7},{%8,%9},{%0,%1,%2,%3};"
        : "+f"(c[0]), "+f"(c[1]), "+f"(c[2]), "+f"(c[3])
        : "r"(a[0]), "r"(a[1]), "r"(a[2]), "r"(a[3]), "r"(b[0]), "r"(b[1]));
}

// ===========================================================================
// kA: zx projection (blocks [0,2048)) + fc1 tf32 GEMM (blocks [2048,2560))
// 256 threads. zx blocks scheduled first (memory-bound) to overlap fc1.
// ===========================================================================
#define ZX_BLOCKS 2048
#define FC1_BLOCKS 512

struct SZX {                        // ~40.2 KB
    uint32_t Ah[64][36], Al[64][36];
    uint32_t Bh[32][84], Bl[32][84];
    float bns[F_], bnh[F_];
};
struct SFC {                        // ~29.7 KB
    uint32_t Ah[128][20];
    uint32_t Al[128][20];
    uint32_t Bh[16][72];
    uint32_t Bl[16][72];
};
union __align__(16) UA { SZX z; SFC f; };

__global__ void __launch_bounds__(256, 2) kA_zx_fc1(
    const float* __restrict__ x,
    const float* __restrict__ bn_gamma, const float* __restrict__ bn_beta,
    const float* __restrict__ bn_mean,  const float* __restrict__ bn_var,
    const float* __restrict__ k1, const float* __restrict__ b1,
    const float* __restrict__ fc1_w, const float* __restrict__ fc1_b)
{
    __shared__ UA u;
    const int tid = threadIdx.x;

    if (blockIdx.x < ZX_BLOCKS) {
        // ======== zx: 64 rows, all 16 experts, tf32 hi/lo 3-pass ============
        const int r0 = blockIdx.x * 64;

        if (tid < F_) {
            float scv = bn_gamma[tid] * rsqrtf(bn_var[tid] + 1e-3f);
            u.z.bns[tid] = scv;
            u.z.bnh[tid] = bn_beta[tid] - bn_mean[tid] * scv;
        }
        __syncthreads();

        {
            const int a_row = tid >> 2;
            const int a_kc  = (tid & 3) * 8;
            #pragma unroll
            for (int j = 0; j < 2; j++) {
                const int col = a_kc + j * 4;
                float4 xv = *(const float4*)(x + (size_t)(r0 + a_row) * F_ + col);
                float vf[4] = {xv.x * u.z.bns[col] + u.z.bnh[col],
                               xv.y * u.z.bns[col + 1] + u.z.bnh[col + 1],
                               xv.z * u.z.bns[col + 2] + u.z.bnh[col + 2],
                               xv.w * u.z.bns[col + 3] + u.z.bnh[col + 3]};
                #pragma unroll
                for (int q = 0; q < 4; q++) {
                    uint32_t hi = f2tf32(vf[q]);
                    u.z.Ah[a_row][col + q] = hi;
                    u.z.Al[a_row][col + q] = f2tf32(vf[q] - __uint_as_float(hi));
                }
            }
        }
        __syncthreads();

        const int lane = tid & 31;
        const int wid = tid >> 5;
        const int g  = lane >> 2;
        const int tg = lane & 3;
        const int warp_m = wid & 3;
        const int warp_n = wid >> 2;

        for (int e = 0; e < E_; e++) {
            for (int idx = tid; idx < F_ * G_; idx += 256) {
                const int k = idx / G_;
                const int n = idx - k * G_;
                float v = k1[(e * F_ + k) * G_ + n];
                uint32_t hi = f2tf32(v);
                u.z.Bh[k][n] = hi;
                u.z.Bl[k][n] = f2tf32(v - __uint_as_float(hi));
            }
            __syncthreads();

            float c[5][4];
            #pragma unroll
            for (int nt = 0; nt < 5; nt++)
                #pragma unroll
                for (int j = 0; j < 4; j++) c[nt][j] = 0.f;

            #pragma unroll
            for (int kk = 0; kk < 32; kk += 8) {
                const int ar = warp_m * 16 + g;
                uint32_t ah[4], al[4];
                ah[0] = u.z.Ah[ar][kk + tg];     ah[1] = u.z.Ah[ar + 8][kk + tg];
                ah[2] = u.z.Ah[ar][kk + tg + 4]; ah[3] = u.z.Ah[ar + 8][kk + tg + 4];
                al[0] = u.z.Al[ar][kk + tg];     al[1] = u.z.Al[ar + 8][kk + tg];
                al[2] = u.z.Al[ar][kk + tg + 4]; al[3] = u.z.Al[ar + 8][kk + tg + 4];
                #pragma unroll
                for (int nt = 0; nt < 5; nt++) {
                    const int bc = warp_n * 40 + nt * 8 + g;
                    uint32_t bh[2], bl[2];
                    bh[0] = u.z.Bh[kk + tg][bc]; bh[1] = u.z.Bh[kk + tg + 4][bc];
                    bl[0] = u.z.Bl[kk + tg][bc]; bl[1] = u.z.Bl[kk + tg + 4][bc];
                    mma_tf32(c[nt], ah, bh);
                    mma_tf32(c[nt], ah, bl);
                    mma_tf32(c[nt], al, bh);
                }
            }

            #pragma unroll
            for (int nt = 0; nt < 5; nt++) {
                const int row = r0 + warp_m * 16 + g;
                const int col = warp_n * 40 + nt * 8 + 2 * tg;
                float2 bb = *(const float2*)&b1[e * G_ + col];
                float2 o0, o1;
                o0.x = c[nt][0] + bb.x;  o0.y = c[nt][1] + bb.y;
                o1.x = c[nt][2] + bb.x;  o1.y = c[nt][3] + bb.y;
                *(float2*)&g_zx[((size_t)e * BT_ + row) * G_ + col]     = o0;
                *(float2*)&g_zx[((size_t)e * BT_ + row + 8) * G_ + col] = o1;
            }
            __syncthreads();
        }
        return;
    }

    // ======== fc1: 128x64 block tile, tf32 hi/lo 3-pass, 256 threads ========
    const int bf = blockIdx.x - ZX_BLOCKS;
    const int m0 = (bf >> 6) * 128;
    const int n0 = (bf & 63) * 64;
    const int lane = tid & 31;
    const int wid = tid >> 5;            // 0..7
    const int g  = lane >> 2;
    const int tg = lane & 3;
    const int warp_m = wid & 3;
    const int warp_n = (wid >> 2) & 1;

    const int a_row = tid >> 1;          // 0..127
    const int a_kc  = (tid & 1) * 8;
    const int b_k   = tid >> 4;          // 0..15
    const int b_nc  = (tid & 15) * 4;

    const float* Ap = x + (size_t)(m0 + a_row) * D_ + a_kc;
    const float* Bp = fc1_w + (size_t)b_k * D_ + n0 + b_nc;

    float4 av0 = *(const float4*)Ap;
    float4 av1 = *(const float4*)(Ap + 4);
    float4 bv  = *(const float4*)Bp;

    float c[2][4][4];
    #pragma unroll
    for (int mt = 0; mt < 2; mt++)
        #pragma unroll
        for (int nt = 0; nt < 4; nt++)
            #pragma unroll
            for (int j = 0; j < 4; j++) c[mt][nt][j] = 0.f;

    const int NS = D_ / 16;
    for (int s = 0; s < NS; s++) {
        {
            float af[8] = {av0.x, av0.y, av0.z, av0.w, av1.x, av1.y, av1.z, av1.w};
            uint32_t hh[8], ll[8];
            #pragma unroll
            for (int j = 0; j < 8; j++) {
                uint32_t hi = f2tf32(af[j]);
                float lo = af[j] - __uint_as_float(hi);
                hh[j] = hi;
                ll[j] = f2tf32(lo);
            }
            *(uint4*)&u.f.Ah[a_row][a_kc]     = make_uint4(hh[0], hh[1], hh[2], hh[3]);
            *(uint4*)&u.f.Ah[a_row][a_kc + 4] = make_uint4(hh[4], hh[5], hh[6], hh[7]);
            *(uint4*)&u.f.Al[a_row][a_kc]     = make_uint4(ll[0], ll[1], ll[2], ll[3]);
            *(uint4*)&u.f.Al[a_row][a_kc + 4] = make_uint4(ll[4], ll[5], ll[6], ll[7]);
            float bff[4] = {bv.x, bv.y, bv.z, bv.w};
            uint32_t bhh[4], bll[4];
            #pragma unroll
            for (int j = 0; j < 4; j++) {
                uint32_t hi = f2tf32(bff[j]);
                float lo = bff[j] - __uint_as_float(hi);
                bhh[j] = hi;
                bll[j] = f2tf32(lo);
            }
            *(uint4*)&u.f.Bh[b_k][b_nc] = make_uint4(bhh[0], bhh[1], bhh[2], bhh[3]);
            *(uint4*)&u.f.Bl[b_k][b_nc] = make_uint4(bll[0], bll[1], bll[2], bll[3]);
        }
        __syncthreads();
        if (s + 1 < NS) {
            av0 = *(const float4*)(Ap + (size_t)(s + 1) * 16);
            av1 = *(const float4*)(Ap + (size_t)(s + 1) * 16 + 4);
            bv  = *(const float4*)(Bp + (size_t)(s + 1) * 16 * D_);
        }
        #pragma unroll
        for (int kk = 0; kk < 16; kk += 8) {
            uint32_t ah[2][4], al[2][4], bh[4][2], bl[4][2];
            #pragma unroll
            for (int mt = 0; mt < 2; mt++) {
                const int ar = warp_m * 32 + mt * 16 + g;
                ah[mt][0] = u.f.Ah[ar][kk + tg];
                ah[mt][1] = u.f.Ah[ar + 8][kk + tg];
                ah[mt][2] = u.f.Ah[ar][kk + tg + 4];
                ah[mt][3] = u.f.Ah[ar + 8][kk + tg + 4];
                al[mt][0] = u.f.Al[ar][kk + tg];
                al[mt][1] = u.f.Al[ar + 8][kk + tg];
                al[mt][2] = u.f.Al[ar][kk + tg + 4];
                al[mt][3] = u.f.Al[ar + 8][kk + tg + 4];
            }
            #pragma unroll
            for (int nt = 0; nt < 4; nt++) {
                const int bc = warp_n * 32 + nt * 8 + g;
                bh[nt][0] = u.f.Bh[kk + tg][bc];
                bh[nt][1] = u.f.Bh[kk + tg + 4][bc];
                bl[nt][0] = u.f.Bl[kk + tg][bc];
                bl[nt][1] = u.f.Bl[kk + tg + 4][bc];
            }
            #pragma unroll
            for (int mt = 0; mt < 2; mt++)
                #pragma unroll
                for (int nt = 0; nt < 4; nt++) {
                    mma_tf32(c[mt][nt], ah[mt], bh[nt]);
                    mma_tf32(c[mt][nt], ah[mt], bl[nt]);
                    mma_tf32(c[mt][nt], al[mt], bh[nt]);
                }
        }
        __syncthreads();
    }

    #pragma unroll
    for (int mt = 0; mt < 2; mt++) {
        #pragma unroll
        for (int nt = 0; nt < 4; nt++) {
            const int row = m0 + warp_m * 32 + mt * 16 + g;
            const int col = n0 + warp_n * 32 + nt * 8 + 2 * tg;
            float2 bb = *(const float2*)&fc1_b[col];
            float2 o0, o1;
            o0.x = fmaxf(c[mt][nt][0] + bb.x, 0.f);
            o0.y = fmaxf(c[mt][nt][1] + bb.y, 0.f);
            o1.x = fmaxf(c[mt][nt][2] + bb.x, 0.f);
            o1.y = fmaxf(c[mt][nt][3] + bb.y, 0.f);
            *(float2*)&g_fc1[(size_t)row * D_ + col]       = o0;
            *(float2*)&g_fc1[(size_t)(row + 8) * D_ + col] = o1;
        }
    }
}

// ===========================================================================
// kB: LSTM recurrence only (1024 blocks, 320 threads, 16 rows/block)
// ===========================================================================
#define LROWS 16
#define LSTM_BLOCKS (E_ * B_ / LROWS)   // 1024

struct __align__(16) SPL {
    float h1[LROWS][24];            // [0..19] live
    float h2[LROWS][24];
    float z1[LROWS][G_];
    float z2[LROWS][G_];
    float zxb[LROWS][G_];           // staged zx(t)
};

__global__ void __launch_bounds__(320, 2) kB_lstm(
    const float* __restrict__ r1,
    const float* __restrict__ k2, const float* __restrict__ r2,
    const float* __restrict__ b2,
    const float* __restrict__ dw, const float* __restrict__ db)
{
    __shared__ SPL u;
    const int tid = threadIdx.x;

    const int e = blockIdx.x >> 6;         // 64 blocks per expert
    const int row0 = (blockIdx.x & 63) * LROWS;

    const int q = tid / G_;                // 0..3 -> rows 4q..4q+3
    const int g = tid - q * G_;            // gate column 0..79
    const int crow = tid / H_;             // cell row 0..15 (== staging row)
    const int cu   = tid - crow * H_;      // cell unit 0..19
    const int sc4  = cu * 4;               // staging float4 col

    float wr1f[H_], wk2f[H_], wr2f[H_];
    #pragma unroll
    for (int j = 0; j < H_; j++) {
        wr1f[j] = r1[(e * H_ + j) * G_ + g];
        wk2f[j] = k2[(e * H_ + j) * G_ + g];
        wr2f[j] = r2[(e * H_ + j) * G_ + g];
    }
    const float bias2 = b2[e * G_ + g];

    for (int idx = tid; idx < 2 * LROWS * 24; idx += 320)
        ((float*)u.h1)[idx] = 0.f;

    const float* pzx = g_zx + ((size_t)e * BT_ + (size_t)(row0 + crow) * T_) * G_ + sc4;
    *(float4*)&u.zxb[crow][sc4] = *(const float4*)pzx;          // zx(0)
    float4 zv = *(const float4*)(pzx + G_);                      // prefetch zx(1)
    __syncthreads();

    float c1 = 0.f, c2 = 0.f;

    for (int t = 0; t <= T_; t++) {
        if (t < T_) {                       // z1 = zx + h1 @ Wr1
            #pragma unroll
            for (int i = 0; i < 4; i++) {
                const int row = 4 * q + i;
                const float4* hp = (const float4*)u.h1[row];
                float4 ha = hp[0], hb = hp[1], hc = hp[2], hd = hp[3], he = hp[4];
                float a0 = u.zxb[row][g];
                float a1 = 0.f, a2 = 0.f, a3 = 0.f;
                a0 += ha.x * wr1f[0];  a1 += ha.y * wr1f[1];
                a2 += ha.z * wr1f[2];  a3 += ha.w * wr1f[3];
                a0 += hb.x * wr1f[4];  a1 += hb.y * wr1f[5];
                a2 += hb.z * wr1f[6];  a3 += hb.w * wr1f[7];
                a0 += hc.x * wr1f[8];  a1 += hc.y * wr1f[9];
                a2 += hc.z * wr1f[10]; a3 += hc.w * wr1f[11];
                a0 += hd.x * wr1f[12]; a1 += hd.y * wr1f[13];
                a2 += hd.z * wr1f[14]; a3 += hd.w * wr1f[15];
                a0 += he.x * wr1f[16]; a1 += he.y * wr1f[17];
                a2 += he.z * wr1f[18]; a3 += he.w * wr1f[19];
                u.z1[row][g] = (a0 + a1) + (a2 + a3);
            }
        }
        if (t >= 1) {                       // z2 = b2 + h1@Wk2 + h2@Wr2
            #pragma unroll
            for (int i = 0; i < 4; i++) {
                const int row = 4 * q + i;
                const float4* h1p = (const float4*)u.h1[row];
                const float4* h2p = (const float4*)u.h2[row];
                float a0 = bias2, a1 = 0.f, a2 = 0.f, a3 = 0.f;
                #pragma unroll
                for (int j5 = 0; j5 < 5; j5++) {
                    float4 v1 = h1p[j5];
                    float4 v2 = h2p[j5];
                    a0 += v1.x * wk2f[4*j5+0];  a1 += v1.y * wk2f[4*j5+1];
                    a2 += v1.z * wk2f[4*j5+2];  a3 += v1.w * wk2f[4*j5+3];
                    a0 += v2.x * wr2f[4*j5+0];  a1 += v2.y * wr2f[4*j5+1];
                    a2 += v2.z * wr2f[4*j5+2];  a3 += v2.w * wr2f[4*j5+3];
                }
                u.z2[row][g] = (a0 + a1) + (a2 + a3);
            }
        }
        __syncthreads();

        if (t < T_) {
            float zi = u.z1[crow][cu];
            float zf = u.z1[crow][H_ + cu];
            float zg = u.z1[crow][2 * H_ + cu];
            float zo = u.z1[crow][3 * H_ + cu];
            c1 = sigmoidf_(zf) * c1 + sigmoidf_(zi) * fmaxf(zg, 0.f);
            u.h1[crow][cu] = sigmoidf_(zo) * fmaxf(c1, 0.f);
        }
        if (t >= 1) {
            float zi = u.z2[crow][cu];
            float zf = u.z2[crow][H_ + cu];
            float zg = u.z2[crow][2 * H_ + cu];
            float zo = u.z2[crow][3 * H_ + cu];
            c2 = sigmoidf_(zf) * c2 + sigmoidf_(zi) * fmaxf(zg, 0.f);
            u.h2[crow][cu] = sigmoidf_(zo) * fmaxf(c2, 0.f);
        }
        if (t + 1 < T_) {
            *(float4*)&u.zxb[crow][sc4] = zv;                    // zx(t+1)
            const int tn = (t + 2 < T_) ? t + 2 : T_ - 1;
            zv = *(const float4*)(pzx + (size_t)tn * G_);
        }
        __syncthreads();
    }

    if (tid < LROWS) {
        float acc = db[e];
        #pragma unroll
        for (int j = 0; j < H_; j++) acc += u.h2[tid][j] * dw[e * H_ + j];
        g_eo[e * B_ + row0 + tid] = acc;
    }
}

// ===========================================================================
// kC: gate logits + softmax -> g_w[b][e]
// ===========================================================================
__global__ void __launch_bounds__(320) kC_gate(
    const float* __restrict__ GW, const float* __restrict__ GB)
{
    __shared__ float red[10][E_];
    __shared__ float sv[E_];
    __shared__ float ev[E_];

    const int b = blockIdx.x;
    const int tid = threadIdx.x;
    float acc[E_];
    #pragma unroll
    for (int e = 0; e < E_; e++) acc[e] = 0.f;

    const float* grow = g_fc1 + (size_t)b * D_;
    for (int k = tid; k < D_; k += 320) {
        float gv = grow[k];
        const float4* wp = (const float4*)(GW + (size_t)k * E_);
        float4 w0 = wp[0], w1 = wp[1], w2 = wp[2], w3 = wp[3];
        acc[0]  += gv * w0.x;  acc[1]  += gv * w0.y;
        acc[2]  += gv * w0.z;  acc[3]  += gv * w0.w;
        acc[4]  += gv * w1.x;  acc[5]  += gv * w1.y;
        acc[6]  += gv * w1.z;  acc[7]  += gv * w1.w;
        acc[8]  += gv * w2.x;  acc[9]  += gv * w2.y;
        acc[10] += gv * w2.z;  acc[11] += gv * w2.w;
        acc[12] += gv * w3.x;  acc[13] += gv * w3.y;
        acc[14] += gv * w3.z;  acc[15] += gv * w3.w;
    }
    #pragma unroll
    for (int e = 0; e < E_; e++) {
        #pragma unroll
        for (int off = 16; off > 0; off >>= 1)
            acc[e] += __shfl_down_sync(0xffffffffu, acc[e], off);
    }
    const int warp = tid >> 5, lane = tid & 31;
    if (lane == 0) {
        #pragma unroll
        for (int e = 0; e < E_; e++) red[warp][e] = acc[e];
    }
    __syncthreads();
    if (tid < E_) {
        float s = GB[tid];
        #pragma unroll
        for (int w = 0; w < 10; w++) s += red[w][tid];
        sv[tid] = s;
    }
    __syncthreads();
    if (tid < E_) {
        float m = sv[0];
        #pragma unroll
        for (int e = 1; e < E_; e++) m = fmaxf(m, sv[e]);
        ev[tid] = expf(sv[tid] - m);
    }
    __syncthreads();
    if (tid < E_) {
        float s = 0.f;
        #pragma unroll
        for (int e = 0; e < E_; e++) s += ev[e];
        g_w[b * E_ + tid] = ev[tid] / s;
    }
}

// ===========================================================================
// kD: combine -> out[b]
// ===========================================================================
__global__ void kD_combine(float* __restrict__ out)
{
    int b = blockIdx.x * blockDim.x + threadIdx.x;
    if (b < B_) {
        float s = 0.f;
        #pragma unroll
        for (int e = 0; e < E_; e++)
            s += g_eo[e * B_ + b] * g_w[b * E_ + e];
        out[b] = s;
    }
}

// ---------------------------------------------------------------------------
extern "C" void kernel_launch(void* const* d_in, const int* in_sizes, int n_in,
                              void* d_out, int out_size)
{
    const float* x        = (const float*)d_in[0];
    const float* bn_gamma = (const float*)d_in[1];
    const float* bn_beta  = (const float*)d_in[2];
    const float* bn_mean  = (const float*)d_in[3];
    const float* bn_var   = (const float*)d_in[4];
    const float* k1       = (const float*)d_in[5];
    const float* r1       = (const float*)d_in[6];
    const float* b1       = (const float*)d_in[7];
    const float* k2       = (const float*)d_in[8];
    const float* r2       = (const float*)d_in[9];
    const float* b2       = (const float*)d_in[10];
    const float* dw       = (const float*)d_in[11];
    const float* db       = (const float*)d_in[12];
    const float* fc1_w    = (const float*)d_in[13];
    const float* fc1_b    = (const float*)d_in[14];
    const float* gate_w   = (const float*)d_in[15];
    const float* gate_b   = (const float*)d_in[16];
    float* out = (float*)d_out;

    // 4 launches per iteration -> ncu (-s 5 -c 1) captures the 6th = kB (LSTM)
    kA_zx_fc1<<<ZX_BLOCKS + FC1_BLOCKS, 256>>>(
        x, bn_gamma, bn_beta, bn_mean, bn_var, k1, b1, fc1_w, fc1_b);

    kB_lstm<<<LSTM_BLOCKS, 320>>>(r1, k2, r2, b2, dw, db);

    kC_gate<<<B_, 320>>>(gate_w, gate_b);

    kD_combine<<<B_ / 256, 256>>>(out);
}

// round 15
// speedup vs baseline: 1.1917x; 1.1917x over previous
#include <cuda_runtime.h>
#include <math.h>
#include <stdint.h>

#define B_ 1024
#define T_ 128
#define F_ 32
#define E_ 16
#define H_ 20
#define G_ 80      // 4*H
#define D_ 4096    // T*F

// scratch (__device__ globals; no allocations allowed)
__device__ float g_fc1[B_ * D_];   // relu(x_flat @ fc1_w + b)
__device__ float g_eo[E_ * B_];    // per-expert outputs

// ---------------- helpers -------------------------------------------------
__device__ __forceinline__ float sigmoidf_(float x) {
    float e = __expf(-x);
    float r;
    asm("rcp.approx.f32 %0, %1;" : "=f"(r) : "f"(1.0f + e));
    return r;
}
__device__ __forceinline__ uint32_t f2tf32(float x) {
    uint32_t r; asm("cvt.rna.tf32.f32 %0, %1;" : "=r"(r) : "f"(x)); return r;
}
// D += A(tf32) * B(tf32), m16n8k8  (fragment mapping validated by fc1)
__device__ __forceinline__ void mma_tf32(float* c, const uint32_t* a, const uint32_t* b) {
    asm("mma.sync.aligned.m16n8k8.row.col.f32.tf32.tf32.f32 "
        "{%0,%1,%2,%3},{%4,%5,%6,%7},{%8,%9},{%0,%1,%2,%3};"
        : "+f"(c[0]), "+f"(c[1]), "+f"(c[2]), "+f"(c[3])
        : "r"(a[0]), "r"(a[1]), "r"(a[2]), "r"(a[3]), "r"(b[0]), "r"(b[1]));
}

// ===========================================================================
// kFat: fc1 tf32 GEMM (blocks [0,512)) + tensor-core LSTM (blocks [512,1536))
// ===========================================================================
#define FC1_BLOCKS 512
#define LROWS 16
#define LSTM_BLOCKS (E_ * B_ / LROWS)   // 1024

struct SFC {                        // fc1 tile buffers (~29.7 KB)
    uint32_t Ah[128][20];
    uint32_t Al[128][20];
    uint32_t Bh[16][72];
    uint32_t Bl[16][72];
};
struct SPL {                        // tensor-lstm buffers (~21.9 KB)
    uint2 Xp[LROWS][34];            // x_t {tf32hi, tf32lo}, BN'd; cols 0..31
    uint2 H1p[LROWS][26];           // h1 {hi,lo}; cols 0..19 live, 20..25 zero
    uint2 H2p[LROWS][26];
    float z1[LROWS][84];            // fp32 gate pre-activations (padded)
    float z2[LROWS][84];
    float bns[F_], bnh[F_];
};
union __align__(16) UA { SFC f; SPL p; };

__global__ void __launch_bounds__(320, 2) kFat(
    const float* __restrict__ x, const float* __restrict__ fc1_w,
    const float* __restrict__ fc1_b,
    const float* __restrict__ bn_gamma, const float* __restrict__ bn_beta,
    const float* __restrict__ bn_mean,  const float* __restrict__ bn_var,
    const float* __restrict__ k1, const float* __restrict__ r1,
    const float* __restrict__ b1,
    const float* __restrict__ k2, const float* __restrict__ r2,
    const float* __restrict__ b2,
    const float* __restrict__ dw, const float* __restrict__ db)
{
    __shared__ UA u;
    const int tid = threadIdx.x;
    const int lane = tid & 31;
    const int w = tid >> 5;              // warp id 0..9
    const int g  = lane >> 2;            // 0..7
    const int tg = lane & 3;             // 0..3

    if (blockIdx.x < FC1_BLOCKS) {
        // ======== fc1: 128x64 block, mma.sync tf32 hi/lo split (proven) =====
        const int m0 = (blockIdx.x >> 6) * 128;
        const int n0 = (blockIdx.x & 63) * 64;
        const bool act = tid < 256;
        const int warp_m = w & 3;
        const int warp_n = (w >> 2) & 1;

        const int a_row = tid >> 1;
        const int a_kc  = (tid & 1) * 8;
        const int b_k   = tid >> 4;
        const int b_nc  = (tid & 15) * 4;

        const float* Ap = x + (size_t)(m0 + a_row) * D_ + a_kc;
        const float* Bp = fc1_w + (size_t)b_k * D_ + n0 + b_nc;

        float4 av0, av1, bv;
        if (act) {
            av0 = *(const float4*)Ap;
            av1 = *(const float4*)(Ap + 4);
            bv  = *(const float4*)Bp;
        }

        float c[2][4][4];
        #pragma unroll
        for (int mt = 0; mt < 2; mt++)
            #pragma unroll
            for (int nt = 0; nt < 4; nt++)
                #pragma unroll
                for (int j = 0; j < 4; j++) c[mt][nt][j] = 0.f;

        const int NS = D_ / 16;
        for (int s = 0; s < NS; s++) {
            if (act) {
                float af[8] = {av0.x, av0.y, av0.z, av0.w, av1.x, av1.y, av1.z, av1.w};
                uint32_t hh[8], ll[8];
                #pragma unroll
                for (int j = 0; j < 8; j++) {
                    uint32_t hi = f2tf32(af[j]);
                    float lo = af[j] - __uint_as_float(hi);
                    hh[j] = hi;
                    ll[j] = f2tf32(lo);
                }
                *(uint4*)&u.f.Ah[a_row][a_kc]     = make_uint4(hh[0], hh[1], hh[2], hh[3]);
                *(uint4*)&u.f.Ah[a_row][a_kc + 4] = make_uint4(hh[4], hh[5], hh[6], hh[7]);
                *(uint4*)&u.f.Al[a_row][a_kc]     = make_uint4(ll[0], ll[1], ll[2], ll[3]);
                *(uint4*)&u.f.Al[a_row][a_kc + 4] = make_uint4(ll[4], ll[5], ll[6], ll[7]);
                float bf[4] = {bv.x, bv.y, bv.z, bv.w};
                uint32_t bhh[4], bll[4];
                #pragma unroll
                for (int j = 0; j < 4; j++) {
                    uint32_t hi = f2tf32(bf[j]);
                    float lo = bf[j] - __uint_as_float(hi);
                    bhh[j] = hi;
                    bll[j] = f2tf32(lo);
                }
                *(uint4*)&u.f.Bh[b_k][b_nc] = make_uint4(bhh[0], bhh[1], bhh[2], bhh[3]);
                *(uint4*)&u.f.Bl[b_k][b_nc] = make_uint4(bll[0], bll[1], bll[2], bll[3]);
            }
            __syncthreads();
            if (act && s + 1 < NS) {
                av0 = *(const float4*)(Ap + (size_t)(s + 1) * 16);
                av1 = *(const float4*)(Ap + (size_t)(s + 1) * 16 + 4);
                bv  = *(const float4*)(Bp + (size_t)(s + 1) * 16 * D_);
            }
            if (act && w < 8) {
                #pragma unroll
                for (int kk = 0; kk < 16; kk += 8) {
                    uint32_t ah[2][4], al[2][4], bh[4][2], bl[4][2];
                    #pragma unroll
                    for (int mt = 0; mt < 2; mt++) {
                        const int ar = warp_m * 32 + mt * 16 + g;
                        ah[mt][0] = u.f.Ah[ar][kk + tg];
                        ah[mt][1] = u.f.Ah[ar + 8][kk + tg];
                        ah[mt][2] = u.f.Ah[ar][kk + tg + 4];
                        ah[mt][3] = u.f.Ah[ar + 8][kk + tg + 4];
                        al[mt][0] = u.f.Al[ar][kk + tg];
                        al[mt][1] = u.f.Al[ar + 8][kk + tg];
                        al[mt][2] = u.f.Al[ar][kk + tg + 4];
                        al[mt][3] = u.f.Al[ar + 8][kk + tg + 4];
                    }
                    #pragma unroll
                    for (int nt = 0; nt < 4; nt++) {
                        const int bc = warp_n * 32 + nt * 8 + g;
                        bh[nt][0] = u.f.Bh[kk + tg][bc];
                        bh[nt][1] = u.f.Bh[kk + tg + 4][bc];
                        bl[nt][0] = u.f.Bl[kk + tg][bc];
                        bl[nt][1] = u.f.Bl[kk + tg + 4][bc];
                    }
                    #pragma unroll
                    for (int mt = 0; mt < 2; mt++)
                        #pragma unroll
                        for (int nt = 0; nt < 4; nt++) {
                            mma_tf32(c[mt][nt], ah[mt], bh[nt]);
                            mma_tf32(c[mt][nt], ah[mt], bl[nt]);
                            mma_tf32(c[mt][nt], al[mt], bh[nt]);
                        }
                }
            }
            __syncthreads();
        }

        if (act && w < 8) {
            #pragma unroll
            for (int mt = 0; mt < 2; mt++) {
                #pragma unroll
                for (int nt = 0; nt < 4; nt++) {
                    const int row = m0 + warp_m * 32 + mt * 16 + g;
                    const int col = n0 + warp_n * 32 + nt * 8 + 2 * tg;
                    float2 bb = *(const float2*)&fc1_b[col];
                    float2 o0, o1;
                    o0.x = fmaxf(c[mt][nt][0] + bb.x, 0.f);
                    o0.y = fmaxf(c[mt][nt][1] + bb.y, 0.f);
                    o1.x = fmaxf(c[mt][nt][2] + bb.x, 0.f);
                    o1.y = fmaxf(c[mt][nt][3] + bb.y, 0.f);
                    *(float2*)&g_fc1[(size_t)row * D_ + col]       = o0;
                    *(float2*)&g_fc1[(size_t)(row + 8) * D_ + col] = o1;
                }
            }
        }
        return;
    }

    // ======== tensor-core LSTM: 16 rows, 10 warps, warp w -> cols [8w,8w+8) =
    const int lb = blockIdx.x - FC1_BLOCKS;
    const int e = lb >> 6;
    const int row0 = (lb & 63) * LROWS;

    const int col  = 8 * w + g;          // B-frag column
    const int col0 = 8 * w + 2 * tg;     // C-frag column base

    // --- preload weight B-fragments (registers, loop-invariant) ------------
    // z1: kt 0..3 = x (k1), kt 4..6 = h1 (r1).   z2: kt 0..2 = h1 (k2), 3..5 = h2 (r2)
    uint32_t w1h[7][2], w1l[7][2], w2h[6][2], w2l[6][2];
    #pragma unroll
    for (int kt = 0; kt < 4; kt++) {
        const int ra = 8 * kt + tg, rb = ra + 4;
        float va = k1[(e * F_ + ra) * G_ + col];
        float vb = k1[(e * F_ + rb) * G_ + col];
        w1h[kt][0] = f2tf32(va); w1l[kt][0] = f2tf32(va - __uint_as_float(w1h[kt][0]));
        w1h[kt][1] = f2tf32(vb); w1l[kt][1] = f2tf32(vb - __uint_as_float(w1h[kt][1]));
    }
    #pragma unroll
    for (int kt = 4; kt < 7; kt++) {
        const int ra = 8 * (kt - 4) + tg, rb = ra + 4;
        float va = r1[(e * H_ + ra) * G_ + col];
        float vb = (rb < H_) ? r1[(e * H_ + rb) * G_ + col] : 0.f;
        w1h[kt][0] = f2tf32(va); w1l[kt][0] = f2tf32(va - __uint_as_float(w1h[kt][0]));
        w1h[kt][1] = f2tf32(vb); w1l[kt][1] = f2tf32(vb - __uint_as_float(w1h[kt][1]));
    }
    #pragma unroll
    for (int kt = 0; kt < 3; kt++) {
        const int ra = 8 * kt + tg, rb = ra + 4;
        float va = k2[(e * H_ + ra) * G_ + col];
        float vb = (rb < H_) ? k2[(e * H_ + rb) * G_ + col] : 0.f;
        w2h[kt][0] = f2tf32(va); w2l[kt][0] = f2tf32(va - __uint_as_float(w2h[kt][0]));
        w2h[kt][1] = f2tf32(vb); w2l[kt][1] = f2tf32(vb - __uint_as_float(w2h[kt][1]));
    }
    #pragma unroll
    for (int kt = 3; kt < 6; kt++) {
        const int ra = 8 * (kt - 3) + tg, rb = ra + 4;
        float va = r2[(e * H_ + ra) * G_ + col];
        float vb = (rb < H_) ? r2[(e * H_ + rb) * G_ + col] : 0.f;
        w2h[kt][0] = f2tf32(va); w2l[kt][0] = f2tf32(va - __uint_as_float(w2h[kt][0]));
        w2h[kt][1] = f2tf32(vb); w2l[kt][1] = f2tf32(vb - __uint_as_float(w2h[kt][1]));
    }
    const float bz1x = b1[e * G_ + col0], bz1y = b1[e * G_ + col0 + 1];
    const float bz2x = b2[e * G_ + col0], bz2y = b2[e * G_ + col0 + 1];

    // cell mapping (proven): 320 threads = 16 rows x 20 units
    const int crow = tid / H_;
    const int cu   = tid - crow * H_;

    if (tid < F_) {
        float scv = bn_gamma[tid] * rsqrtf(bn_var[tid] + 1e-3f);
        u.p.bns[tid] = scv;
        u.p.bnh[tid] = bn_beta[tid] - bn_mean[tid] * scv;
    }
    // zero H1p/H2p (incl. padding cols)
    for (int idx = tid; idx < 2 * LROWS * 26; idx += 320)
        ((uint2*)u.p.H1p)[idx] = make_uint2(0u, 0u);
    __syncthreads();

    // x stagers: entry tid and (tid<192) entry 320+tid
    const int s1r = tid >> 5,        s1f = tid & 31;
    const int s2r = 10 + (tid >> 5), s2f = tid & 31;
    const bool has2 = tid < 192;
    const float* px1 = x + (size_t)(row0 + s1r) * D_ + s1f;
    const float* px2 = x + (size_t)(row0 + s2r) * D_ + s2f;
    const float sc1 = u.p.bns[s1f], sh1 = u.p.bnh[s1f];
    {
        float v = px1[0] * sc1 + sh1;
        uint32_t hi = f2tf32(v);
        u.p.Xp[s1r][s1f] = make_uint2(hi, f2tf32(v - __uint_as_float(hi)));
        if (has2) {
            float v2 = px2[0] * sc1 + sh1;   // sc depends only on f == s1f == s2f
            uint32_t hi2 = f2tf32(v2);
            u.p.Xp[s2r][s2f] = make_uint2(hi2, f2tf32(v2 - __uint_as_float(hi2)));
        }
    }
    float xv1 = px1[F_];
    float xv2 = has2 ? px2[F_] : 0.f;
    __syncthreads();

    float c1 = 0.f, c2 = 0.f;   // cell states (fp32, registers)

    #define LOAD_AFRAG(arr, kbase)                                            \
        { uint2 q0 = u.p.arr[g][(kbase) + tg];                                \
          uint2 q1 = u.p.arr[g + 8][(kbase) + tg];                            \
          uint2 q2 = u.p.arr[g][(kbase) + tg + 4];                            \
          uint2 q3 = u.p.arr[g + 8][(kbase) + tg + 4];                        \
          ah[0] = q0.x; ah[1] = q1.x; ah[2] = q2.x; ah[3] = q3.x;             \
          al[0] = q0.y; al[1] = q1.y; al[2] = q2.y; al[3] = q3.y; }

    for (int t = 0; t <= T_; t++) {
        // ---- phase A: tensor-core gate pre-activations ---------------------
        uint32_t ah[4], al[4];
        if (t < T_) {                       // z1(t) = b1 + x_t@Wk1 + h1(t-1)@Wr1
            float cfr[4] = {bz1x, bz1y, bz1x, bz1y};
            #pragma unroll
            for (int kt = 0; kt < 4; kt++) {
                LOAD_AFRAG(Xp, 8 * kt);
                mma_tf32(cfr, ah, w1h[kt]);
                mma_tf32(cfr, ah, w1l[kt]);
                mma_tf32(cfr, al, w1h[kt]);
            }
            #pragma unroll
            for (int kt = 4; kt < 7; kt++) {
                LOAD_AFRAG(H1p, 8 * (kt - 4));
                mma_tf32(cfr, ah, w1h[kt]);
                mma_tf32(cfr, ah, w1l[kt]);
                mma_tf32(cfr, al, w1h[kt]);
            }
            *(float2*)&u.p.z1[g][col0]     = make_float2(cfr[0], cfr[1]);
            *(float2*)&u.p.z1[g + 8][col0] = make_float2(cfr[2], cfr[3]);
        }
        if (t >= 1) {                       // z2(t-1) = b2 + h1(t-1)@Wk2 + h2(t-2)@Wr2
            float cfr[4] = {bz2x, bz2y, bz2x, bz2y};
            #pragma unroll
            for (int kt = 0; kt < 3; kt++) {
                LOAD_AFRAG(H1p, 8 * kt);
                mma_tf32(cfr, ah, w2h[kt]);
                mma_tf32(cfr, ah, w2l[kt]);
                mma_tf32(cfr, al, w2h[kt]);
            }
            #pragma unroll
            for (int kt = 3; kt < 6; kt++) {
                LOAD_AFRAG(H2p, 8 * (kt - 3));
                mma_tf32(cfr, ah, w2h[kt]);
                mma_tf32(cfr, ah, w2l[kt]);
                mma_tf32(cfr, al, w2h[kt]);
            }
            *(float2*)&u.p.z2[g][col0]     = make_float2(cfr[0], cfr[1]);
            *(float2*)&u.p.z2[g + 8][col0] = make_float2(cfr[2], cfr[3]);
        }
        __syncthreads();

        // ---- phase B: cells (fp32 state) + h->tf32 pack + x staging --------
        if (t < T_) {
            float zi = u.p.z1[crow][cu];
            float zf = u.p.z1[crow][H_ + cu];
            float zg = u.p.z1[crow][2 * H_ + cu];
            float zo = u.p.z1[crow][3 * H_ + cu];
            c1 = sigmoidf_(zf) * c1 + sigmoidf_(zi) * fmaxf(zg, 0.f);
            float h = sigmoidf_(zo) * fmaxf(c1, 0.f);
            uint32_t hi = f2tf32(h);
            u.p.H1p[crow][cu] = make_uint2(hi, f2tf32(h - __uint_as_float(hi)));
        }
        if (t >= 1) {
            float zi = u.p.z2[crow][cu];
            float zf = u.p.z2[crow][H_ + cu];
            float zg = u.p.z2[crow][2 * H_ + cu];
            float zo = u.p.z2[crow][3 * H_ + cu];
            c2 = sigmoidf_(zf) * c2 + sigmoidf_(zi) * fmaxf(zg, 0.f);
            float h = sigmoidf_(zo) * fmaxf(c2, 0.f);
            uint32_t hi = f2tf32(h);
            u.p.H2p[crow][cu] = make_uint2(hi, f2tf32(h - __uint_as_float(hi)));
        }
        if (t + 1 < T_) {
            const int tn = (t + 2 < T_) ? t + 2 : T_ - 1;
            float v = xv1 * sc1 + sh1;
            uint32_t hi = f2tf32(v);
            u.p.Xp[s1r][s1f] = make_uint2(hi, f2tf32(v - __uint_as_float(hi)));
            xv1 = px1[(size_t)tn * F_];
            if (has2) {
                float v2 = xv2 * sc1 + sh1;
                uint32_t hi2 = f2tf32(v2);
                u.p.Xp[s2r][s2f] = make_uint2(hi2, f2tf32(v2 - __uint_as_float(hi2)));
                xv2 = px2[(size_t)tn * F_];
            }
        }
        __syncthreads();
    }
    #undef LOAD_AFRAG

    // dense head: eo[e,b] = h2(T-1) @ dw[e] + db[e]   (h2 = hi + lo)
    if (tid < LROWS) {
        float acc = db[e];
        #pragma unroll
        for (int j = 0; j < H_; j++) {
            uint2 hv = u.p.H2p[tid][j];
            acc += (__uint_as_float(hv.x) + __uint_as_float(hv.y)) * dw[e * H_ + j];
        }
        g_eo[e * B_ + row0 + tid] = acc;
    }
}

// ===========================================================================
// kC: gate (fc1 row @ gate_w, softmax) + combine -> out[b]   (proven)
// ===========================================================================
__global__ void __launch_bounds__(320) kC_gate_combine(
    const float* __restrict__ GW, const float* __restrict__ GB,
    float* __restrict__ out)
{
    __shared__ float red[10][E_];
    __shared__ float sv[E_];
    __shared__ float ev[E_];
    __shared__ float part[E_];

    const int b = blockIdx.x;
    const int tid = threadIdx.x;
    float acc[E_];
    #pragma unroll
    for (int e = 0; e < E_; e++) acc[e] = 0.f;

    const float* grow = g_fc1 + (size_t)b * D_;
    for (int k = tid; k < D_; k += 320) {
        float gv = grow[k];
        const float4* wp = (const float4*)(GW + (size_t)k * E_);
        float4 w0 = wp[0], w1 = wp[1], w2 = wp[2], w3 = wp[3];
        acc[0]  += gv * w0.x;  acc[1]  += gv * w0.y;
        acc[2]  += gv * w0.z;  acc[3]  += gv * w0.w;
        acc[4]  += gv * w1.x;  acc[5]  += gv * w1.y;
        acc[6]  += gv * w1.z;  acc[7]  += gv * w1.w;
        acc[8]  += gv * w2.x;  acc[9]  += gv * w2.y;
        acc[10] += gv * w2.z;  acc[11] += gv * w2.w;
        acc[12] += gv * w3.x;  acc[13] += gv * w3.y;
        acc[14] += gv * w3.z;  acc[15] += gv * w3.w;
    }
    #pragma unroll
    for (int e = 0; e < E_; e++) {
        #pragma unroll
        for (int off = 16; off > 0; off >>= 1)
            acc[e] += __shfl_down_sync(0xffffffffu, acc[e], off);
    }
    const int warp = tid >> 5, lane = tid & 31;
    if (lane == 0) {
        #pragma unroll
        for (int e = 0; e < E_; e++) red[warp][e] = acc[e];
    }
    __syncthreads();
    if (tid < E_) {
        float s = GB[tid];
        #pragma unroll
        for (int w = 0; w < 10; w++) s += red[w][tid];
        sv[tid] = s;
    }
    __syncthreads();
    if (tid < E_) {
        float m = sv[0];
        #pragma unroll
        for (int e = 1; e < E_; e++) m = fmaxf(m, sv[e]);
        ev[tid] = expf(sv[tid] - m);
    }
    __syncthreads();
    if (tid < E_) {
        float s = 0.f;
        #pragma unroll
        for (int e = 0; e < E_; e++) s += ev[e];
        part[tid] = (ev[tid] / s) * g_eo[tid * B_ + b];
    }
    __syncthreads();
    if (tid == 0) {
        float s = 0.f;
        #pragma unroll
        for (int e = 0; e < E_; e++) s += part[e];
        out[b] = s;
    }
}

// ---------------------------------------------------------------------------
extern "C" void kernel_launch(void* const* d_in, const int* in_sizes, int n_in,
                              void* d_out, int out_size)
{
    const float* x        = (const float*)d_in[0];
    const float* bn_gamma = (const float*)d_in[1];
    const float* bn_beta  = (const float*)d_in[2];
    const float* bn_mean  = (const float*)d_in[3];
    const float* bn_var   = (const float*)d_in[4];
    const float* k1       = (const float*)d_in[5];
    const float* r1       = (const float*)d_in[6];
    const float* b1       = (const float*)d_in[7];
    const float* k2       = (const float*)d_in[8];
    const float* r2       = (const float*)d_in[9];
    const float* b2       = (const float*)d_in[10];
    const float* dw       = (const float*)d_in[11];
    const float* db       = (const float*)d_in[12];
    const float* fc1_w    = (const float*)d_in[13];
    const float* fc1_b    = (const float*)d_in[14];
    const float* gate_w   = (const float*)d_in[15];
    const float* gate_b   = (const float*)d_in[16];
    float* out = (float*)d_out;

    kFat<<<FC1_BLOCKS + LSTM_BLOCKS, 320>>>(
        x, fc1_w, fc1_b, bn_gamma, bn_beta, bn_mean, bn_var,
        k1, r1, b1, k2, r2, b2, dw, db);

    kC_gate_combine<<<B_, 320>>>(gate_w, gate_b, out);
}

// round 16
// speedup vs baseline: 1.2964x; 1.0878x over previous
#include <cuda_runtime.h>
#include <math.h>
#include <stdint.h>

#define B_ 1024
#define T_ 128
#define F_ 32
#define E_ 16
#define H_ 20
#define G_ 80      // 4*H
#define D_ 4096    // T*F

// scratch (__device__ globals; no allocations allowed)
__device__ float g_fc1[B_ * D_];   // relu(x_flat @ fc1_w + b)
__device__ float g_eo[E_ * B_];    // per-expert outputs

// ---------------- helpers -------------------------------------------------
__device__ __forceinline__ float sigmoidf_(float x) {
    float e = __expf(-x);
    float r;
    asm("rcp.approx.f32 %0, %1;" : "=f"(r) : "f"(1.0f + e));
    return r;
}
__device__ __forceinline__ uint32_t f2tf32(float x) {
    uint32_t r; asm("cvt.rna.tf32.f32 %0, %1;" : "=r"(r) : "f"(x)); return r;
}
// D += A(tf32) * B(tf32), m16n8k8  (fragment mapping validated by fc1)
__device__ __forceinline__ void mma_tf32(float* c, const uint32_t* a, const uint32_t* b) {
    asm("mma.sync.aligned.m16n8k8.row.col.f32.tf32.tf32.f32 "
        "{%0,%1,%2,%3},{%4,%5,%6,%7},{%8,%9},{%0,%1,%2,%3};"
        : "+f"(c[0]), "+f"(c[1]), "+f"(c[2]), "+f"(c[3])
        : "r"(a[0]), "r"(a[1]), "r"(a[2]), "r"(a[3]), "r"(b[0]), "r"(b[1]));
}

// ===========================================================================
// kFat: fc1 tf32 GEMM (blocks [0,512)) + tensor-core LSTM (blocks [512,1536))
// ===========================================================================
#define FC1_BLOCKS 512
#define LROWS 16
#define LSTM_BLOCKS (E_ * B_ / LROWS)   // 1024

struct SFC {                        // fc1 tile buffers (~29.7 KB)
    uint32_t Ah[128][20];
    uint32_t Al[128][20];
    uint32_t Bh[16][72];
    uint32_t Bl[16][72];
};
struct SPL {                        // tensor-lstm buffers (~21.9 KB)
    uint2 Xp[LROWS][34];            // x_t {tf32hi, tf32lo}, BN'd; cols 0..31
    uint2 H1p[LROWS][26];           // h1 {hi,lo}; cols 0..19 live, 20..25 zero
    uint2 H2p[LROWS][26];
    float z1[LROWS][84];            // fp32 gate pre-activations (padded)
    float z2[LROWS][84];
    float bns[F_], bnh[F_];
};
union __align__(16) UA { SFC f; SPL p; };

__global__ void __launch_bounds__(320, 2) kFat(
    const float* __restrict__ x, const float* __restrict__ fc1_w,
    const float* __restrict__ fc1_b,
    const float* __restrict__ bn_gamma, const float* __restrict__ bn_beta,
    const float* __restrict__ bn_mean,  const float* __restrict__ bn_var,
    const float* __restrict__ k1, const float* __restrict__ r1,
    const float* __restrict__ b1,
    const float* __restrict__ k2, const float* __restrict__ r2,
    const float* __restrict__ b2,
    const float* __restrict__ dw, const float* __restrict__ db)
{
    __shared__ UA u;
    const int tid = threadIdx.x;
    const int lane = tid & 31;
    const int w = tid >> 5;              // warp id 0..9
    const int g  = lane >> 2;            // 0..7
    const int tg = lane & 3;             // 0..3

    if (blockIdx.x < FC1_BLOCKS) {
        // ======== fc1: 128x64 block, mma.sync tf32 hi/lo split (proven, 3-pass)
        const int m0 = (blockIdx.x >> 6) * 128;
        const int n0 = (blockIdx.x & 63) * 64;
        const bool act = tid < 256;
        const int warp_m = w & 3;
        const int warp_n = (w >> 2) & 1;

        const int a_row = tid >> 1;
        const int a_kc  = (tid & 1) * 8;
        const int b_k   = tid >> 4;
        const int b_nc  = (tid & 15) * 4;

        const float* Ap = x + (size_t)(m0 + a_row) * D_ + a_kc;
        const float* Bp = fc1_w + (size_t)b_k * D_ + n0 + b_nc;

        float4 av0, av1, bv;
        if (act) {
            av0 = *(const float4*)Ap;
            av1 = *(const float4*)(Ap + 4);
            bv  = *(const float4*)Bp;
        }

        float c[2][4][4];
        #pragma unroll
        for (int mt = 0; mt < 2; mt++)
            #pragma unroll
            for (int nt = 0; nt < 4; nt++)
                #pragma unroll
                for (int j = 0; j < 4; j++) c[mt][nt][j] = 0.f;

        const int NS = D_ / 16;
        for (int s = 0; s < NS; s++) {
            if (act) {
                float af[8] = {av0.x, av0.y, av0.z, av0.w, av1.x, av1.y, av1.z, av1.w};
                uint32_t hh[8], ll[8];
                #pragma unroll
                for (int j = 0; j < 8; j++) {
                    uint32_t hi = f2tf32(af[j]);
                    float lo = af[j] - __uint_as_float(hi);
                    hh[j] = hi;
                    ll[j] = f2tf32(lo);
                }
                *(uint4*)&u.f.Ah[a_row][a_kc]     = make_uint4(hh[0], hh[1], hh[2], hh[3]);
                *(uint4*)&u.f.Ah[a_row][a_kc + 4] = make_uint4(hh[4], hh[5], hh[6], hh[7]);
                *(uint4*)&u.f.Al[a_row][a_kc]     = make_uint4(ll[0], ll[1], ll[2], ll[3]);
                *(uint4*)&u.f.Al[a_row][a_kc + 4] = make_uint4(ll[4], ll[5], ll[6], ll[7]);
                float bf[4] = {bv.x, bv.y, bv.z, bv.w};
                uint32_t bhh[4], bll[4];
                #pragma unroll
                for (int j = 0; j < 4; j++) {
                    uint32_t hi = f2tf32(bf[j]);
                    float lo = bf[j] - __uint_as_float(hi);
                    bhh[j] = hi;
                    bll[j] = f2tf32(lo);
                }
                *(uint4*)&u.f.Bh[b_k][b_nc] = make_uint4(bhh[0], bhh[1], bhh[2], bhh[3]);
                *(uint4*)&u.f.Bl[b_k][b_nc] = make_uint4(bll[0], bll[1], bll[2], bll[3]);
            }
            __syncthreads();
            if (act && s + 1 < NS) {
                av0 = *(const float4*)(Ap + (size_t)(s + 1) * 16);
                av1 = *(const float4*)(Ap + (size_t)(s + 1) * 16 + 4);
                bv  = *(const float4*)(Bp + (size_t)(s + 1) * 16 * D_);
            }
            if (act && w < 8) {
                #pragma unroll
                for (int kk = 0; kk < 16; kk += 8) {
                    uint32_t ah[2][4], al[2][4], bh[4][2], bl[4][2];
                    #pragma unroll
                    for (int mt = 0; mt < 2; mt++) {
                        const int ar = warp_m * 32 + mt * 16 + g;
                        ah[mt][0] = u.f.Ah[ar][kk + tg];
                        ah[mt][1] = u.f.Ah[ar + 8][kk + tg];
                        ah[mt][2] = u.f.Ah[ar][kk + tg + 4];
                        ah[mt][3] = u.f.Ah[ar + 8][kk + tg + 4];
                        al[mt][0] = u.f.Al[ar][kk + tg];
                        al[mt][1] = u.f.Al[ar + 8][kk + tg];
                        al[mt][2] = u.f.Al[ar][kk + tg + 4];
                        al[mt][3] = u.f.Al[ar + 8][kk + tg + 4];
                    }
                    #pragma unroll
                    for (int nt = 0; nt < 4; nt++) {
                        const int bc = warp_n * 32 + nt * 8 + g;
                        bh[nt][0] = u.f.Bh[kk + tg][bc];
                        bh[nt][1] = u.f.Bh[kk + tg + 4][bc];
                        bl[nt][0] = u.f.Bl[kk + tg][bc];
                        bl[nt][1] = u.f.Bl[kk + tg + 4][bc];
                    }
                    #pragma unroll
                    for (int mt = 0; mt < 2; mt++)
                        #pragma unroll
                        for (int nt = 0; nt < 4; nt++) {
                            mma_tf32(c[mt][nt], ah[mt], bh[nt]);
                            mma_tf32(c[mt][nt], ah[mt], bl[nt]);
                            mma_tf32(c[mt][nt], al[mt], bh[nt]);
                        }
                }
            }
            __syncthreads();
        }

        if (act && w < 8) {
            #pragma unroll
            for (int mt = 0; mt < 2; mt++) {
                #pragma unroll
                for (int nt = 0; nt < 4; nt++) {
                    const int row = m0 + warp_m * 32 + mt * 16 + g;
                    const int col = n0 + warp_n * 32 + nt * 8 + 2 * tg;
                    float2 bb = *(const float2*)&fc1_b[col];
                    float2 o0, o1;
                    o0.x = fmaxf(c[mt][nt][0] + bb.x, 0.f);
                    o0.y = fmaxf(c[mt][nt][1] + bb.y, 0.f);
                    o1.x = fmaxf(c[mt][nt][2] + bb.x, 0.f);
                    o1.y = fmaxf(c[mt][nt][3] + bb.y, 0.f);
                    *(float2*)&g_fc1[(size_t)row * D_ + col]       = o0;
                    *(float2*)&g_fc1[(size_t)(row + 8) * D_ + col] = o1;
                }
            }
        }
        return;
    }

    // ======== tensor-core LSTM: 16 rows, 10 warps, warp w -> cols [8w,8w+8)
    // 2-pass precision: A (x/h) kept hi/lo split; weights tf32-hi only.
    const int lb = blockIdx.x - FC1_BLOCKS;
    const int e = lb >> 6;
    const int row0 = (lb & 63) * LROWS;

    const int col  = 8 * w + g;          // B-frag column
    const int col0 = 8 * w + 2 * tg;     // C-frag column base

    // --- preload weight B-fragments (tf32-hi, registers, loop-invariant) ---
    // z1: kt 0..3 = x (k1), kt 4..6 = h1 (r1).   z2: kt 0..2 = h1 (k2), 3..5 = h2 (r2)
    uint32_t w1h[7][2], w2h[6][2];
    #pragma unroll
    for (int kt = 0; kt < 4; kt++) {
        const int ra = 8 * kt + tg, rb = ra + 4;
        w1h[kt][0] = f2tf32(k1[(e * F_ + ra) * G_ + col]);
        w1h[kt][1] = f2tf32(k1[(e * F_ + rb) * G_ + col]);
    }
    #pragma unroll
    for (int kt = 4; kt < 7; kt++) {
        const int ra = 8 * (kt - 4) + tg, rb = ra + 4;
        w1h[kt][0] = f2tf32(r1[(e * H_ + ra) * G_ + col]);
        w1h[kt][1] = f2tf32((rb < H_) ? r1[(e * H_ + rb) * G_ + col] : 0.f);
    }
    #pragma unroll
    for (int kt = 0; kt < 3; kt++) {
        const int ra = 8 * kt + tg, rb = ra + 4;
        w2h[kt][0] = f2tf32(k2[(e * H_ + ra) * G_ + col]);
        w2h[kt][1] = f2tf32((rb < H_) ? k2[(e * H_ + rb) * G_ + col] : 0.f);
    }
    #pragma unroll
    for (int kt = 3; kt < 6; kt++) {
        const int ra = 8 * (kt - 3) + tg, rb = ra + 4;
        w2h[kt][0] = f2tf32(r2[(e * H_ + ra) * G_ + col]);
        w2h[kt][1] = f2tf32((rb < H_) ? r2[(e * H_ + rb) * G_ + col] : 0.f);
    }
    const float bz1x = b1[e * G_ + col0], bz1y = b1[e * G_ + col0 + 1];
    const float bz2x = b2[e * G_ + col0], bz2y = b2[e * G_ + col0 + 1];

    // cell mapping (proven): 320 threads = 16 rows x 20 units
    const int crow = tid / H_;
    const int cu   = tid - crow * H_;

    if (tid < F_) {
        float scv = bn_gamma[tid] * rsqrtf(bn_var[tid] + 1e-3f);
        u.p.bns[tid] = scv;
        u.p.bnh[tid] = bn_beta[tid] - bn_mean[tid] * scv;
    }
    for (int idx = tid; idx < 2 * LROWS * 26; idx += 320)
        ((uint2*)u.p.H1p)[idx] = make_uint2(0u, 0u);
    __syncthreads();

    // x stagers: entry tid and (tid<192) entry 320+tid
    const int s1r = tid >> 5,        s1f = tid & 31;
    const int s2r = 10 + (tid >> 5), s2f = tid & 31;
    const bool has2 = tid < 192;
    const float* px1 = x + (size_t)(row0 + s1r) * D_ + s1f;
    const float* px2 = x + (size_t)(row0 + s2r) * D_ + s2f;
    const float sc1 = u.p.bns[s1f], sh1 = u.p.bnh[s1f];
    {
        float v = px1[0] * sc1 + sh1;
        uint32_t hi = f2tf32(v);
        u.p.Xp[s1r][s1f] = make_uint2(hi, f2tf32(v - __uint_as_float(hi)));
        if (has2) {
            float v2 = px2[0] * sc1 + sh1;
            uint32_t hi2 = f2tf32(v2);
            u.p.Xp[s2r][s2f] = make_uint2(hi2, f2tf32(v2 - __uint_as_float(hi2)));
        }
    }
    float xv1 = px1[F_];
    float xv2 = has2 ? px2[F_] : 0.f;
    __syncthreads();

    float c1 = 0.f, c2 = 0.f;   // cell states (fp32, registers)

    #define LOAD_AFRAG(arr, kbase)                                            \
        { uint2 q0 = u.p.arr[g][(kbase) + tg];                                \
          uint2 q1 = u.p.arr[g + 8][(kbase) + tg];                            \
          uint2 q2 = u.p.arr[g][(kbase) + tg + 4];                            \
          uint2 q3 = u.p.arr[g + 8][(kbase) + tg + 4];                        \
          ah[0] = q0.x; ah[1] = q1.x; ah[2] = q2.x; ah[3] = q3.x;             \
          al[0] = q0.y; al[1] = q1.y; al[2] = q2.y; al[3] = q3.y; }

    for (int t = 0; t <= T_; t++) {
        // ---- phase A: tensor-core gate pre-activations (2-pass) ------------
        uint32_t ah[4], al[4];
        if (t < T_) {                       // z1(t) = b1 + x_t@Wk1 + h1(t-1)@Wr1
            float cfr[4] = {bz1x, bz1y, bz1x, bz1y};
            #pragma unroll
            for (int kt = 0; kt < 4; kt++) {
                LOAD_AFRAG(Xp, 8 * kt);
                mma_tf32(cfr, ah, w1h[kt]);
                mma_tf32(cfr, al, w1h[kt]);
            }
            #pragma unroll
            for (int kt = 4; kt < 7; kt++) {
                LOAD_AFRAG(H1p, 8 * (kt - 4));
                mma_tf32(cfr, ah, w1h[kt]);
                mma_tf32(cfr, al, w1h[kt]);
            }
            *(float2*)&u.p.z1[g][col0]     = make_float2(cfr[0], cfr[1]);
            *(float2*)&u.p.z1[g + 8][col0] = make_float2(cfr[2], cfr[3]);
        }
        if (t >= 1) {                       // z2(t-1) = b2 + h1(t-1)@Wk2 + h2(t-2)@Wr2
            float cfr[4] = {bz2x, bz2y, bz2x, bz2y};
            #pragma unroll
            for (int kt = 0; kt < 3; kt++) {
                LOAD_AFRAG(H1p, 8 * kt);
                mma_tf32(cfr, ah, w2h[kt]);
                mma_tf32(cfr, al, w2h[kt]);
            }
            #pragma unroll
            for (int kt = 3; kt < 6; kt++) {
                LOAD_AFRAG(H2p, 8 * (kt - 3));
                mma_tf32(cfr, ah, w2h[kt]);
                mma_tf32(cfr, al, w2h[kt]);
            }
            *(float2*)&u.p.z2[g][col0]     = make_float2(cfr[0], cfr[1]);
            *(float2*)&u.p.z2[g + 8][col0] = make_float2(cfr[2], cfr[3]);
        }
        __syncthreads();

        // ---- phase B: cells (fp32 state) + h->tf32 pack + x staging --------
        if (t < T_) {
            float zi = u.p.z1[crow][cu];
            float zf = u.p.z1[crow][H_ + cu];
            float zg = u.p.z1[crow][2 * H_ + cu];
            float zo = u.p.z1[crow][3 * H_ + cu];
            c1 = sigmoidf_(zf) * c1 + sigmoidf_(zi) * fmaxf(zg, 0.f);
            float h = sigmoidf_(zo) * fmaxf(c1, 0.f);
            uint32_t hi = f2tf32(h);
            u.p.H1p[crow][cu] = make_uint2(hi, f2tf32(h - __uint_as_float(hi)));
        }
        if (t >= 1) {
            float zi = u.p.z2[crow][cu];
            float zf = u.p.z2[crow][H_ + cu];
            float zg = u.p.z2[crow][2 * H_ + cu];
            float zo = u.p.z2[crow][3 * H_ + cu];
            c2 = sigmoidf_(zf) * c2 + sigmoidf_(zi) * fmaxf(zg, 0.f);
            float h = sigmoidf_(zo) * fmaxf(c2, 0.f);
            uint32_t hi = f2tf32(h);
            u.p.H2p[crow][cu] = make_uint2(hi, f2tf32(h - __uint_as_float(hi)));
        }
        if (t + 1 < T_) {
            const int tn = (t + 2 < T_) ? t + 2 : T_ - 1;
            float v = xv1 * sc1 + sh1;
            uint32_t hi = f2tf32(v);
            u.p.Xp[s1r][s1f] = make_uint2(hi, f2tf32(v - __uint_as_float(hi)));
            xv1 = px1[(size_t)tn * F_];
            if (has2) {
                float v2 = xv2 * sc1 + sh1;
                uint32_t hi2 = f2tf32(v2);
                u.p.Xp[s2r][s2f] = make_uint2(hi2, f2tf32(v2 - __uint_as_float(hi2)));
                xv2 = px2[(size_t)tn * F_];
            }
        }
        __syncthreads();
    }
    #undef LOAD_AFRAG

    // dense head: eo[e,b] = h2(T-1) @ dw[e] + db[e]   (h2 = hi + lo)
    if (tid < LROWS) {
        float acc = db[e];
        #pragma unroll
        for (int j = 0; j < H_; j++) {
            uint2 hv = u.p.H2p[tid][j];
            acc += (__uint_as_float(hv.x) + __uint_as_float(hv.y)) * dw[e * H_ + j];
        }
        g_eo[e * B_ + row0 + tid] = acc;
    }
}

// ===========================================================================
// kC: gate (fc1 row @ gate_w, softmax) + combine -> out[b]   (proven)
// ===========================================================================
__global__ void __launch_bounds__(320) kC_gate_combine(
    const float* __restrict__ GW, const float* __restrict__ GB,
    float* __restrict__ out)
{
    __shared__ float red[10][E_];
    __shared__ float sv[E_];
    __shared__ float ev[E_];
    __shared__ float part[E_];

    const int b = blockIdx.x;
    const int tid = threadIdx.x;
    float acc[E_];
    #pragma unroll
    for (int e = 0; e < E_; e++) acc[e] = 0.f;

    const float* grow = g_fc1 + (size_t)b * D_;
    for (int k = tid; k < D_; k += 320) {
        float gv = grow[k];
        const float4* wp = (const float4*)(GW + (size_t)k * E_);
        float4 w0 = wp[0], w1 = wp[1], w2 = wp[2], w3 = wp[3];
        acc[0]  += gv * w0.x;  acc[1]  += gv * w0.y;
        acc[2]  += gv * w0.z;  acc[3]  += gv * w0.w;
        acc[4]  += gv * w1.x;  acc[5]  += gv * w1.y;
        acc[6]  += gv * w1.z;  acc[7]  += gv * w1.w;
        acc[8]  += gv * w2.x;  acc[9]  += gv * w2.y;
        acc[10] += gv * w2.z;  acc[11] += gv * w2.w;
        acc[12] += gv * w3.x;  acc[13] += gv * w3.y;
        acc[14] += gv * w3.z;  acc[15] += gv * w3.w;
    }
    #pragma unroll
    for (int e = 0; e < E_; e++) {
        #pragma unroll
        for (int off = 16; off > 0; off >>= 1)
            acc[e] += __shfl_down_sync(0xffffffffu, acc[e], off);
    }
    const int warp = tid >> 5, lane = tid & 31;
    if (lane == 0) {
        #pragma unroll
        for (int e = 0; e < E_; e++) red[warp][e] = acc[e];
    }
    __syncthreads();
    if (tid < E_) {
        float s = GB[tid];
        #pragma unroll
        for (int w = 0; w < 10; w++) s += red[w][tid];
        sv[tid] = s;
    }
    __syncthreads();
    if (tid < E_) {
        float m = sv[0];
        #pragma unroll
        for (int e = 1; e < E_; e++) m = fmaxf(m, sv[e]);
        ev[tid] = expf(sv[tid] - m);
    }
    __syncthreads();
    if (tid < E_) {
        float s = 0.f;
        #pragma unroll
        for (int e = 0; e < E_; e++) s += ev[e];
        part[tid] = (ev[tid] / s) * g_eo[tid * B_ + b];
    }
    __syncthreads();
    if (tid == 0) {
        float s = 0.f;
        #pragma unroll
        for (int e = 0; e < E_; e++) s += part[e];
        out[b] = s;
    }
}

// ---------------------------------------------------------------------------
extern "C" void kernel_launch(void* const* d_in, const int* in_sizes, int n_in,
                              void* d_out, int out_size)
{
    const float* x        = (const float*)d_in[0];
    const float* bn_gamma = (const float*)d_in[1];
    const float* bn_beta  = (const float*)d_in[2];
    const float* bn_mean  = (const float*)d_in[3];
    const float* bn_var   = (const float*)d_in[4];
    const float* k1       = (const float*)d_in[5];
    const float* r1       = (const float*)d_in[6];
    const float* b1       = (const float*)d_in[7];
    const float* k2       = (const float*)d_in[8];
    const float* r2       = (const float*)d_in[9];
    const float* b2       = (const float*)d_in[10];
    const float* dw       = (const float*)d_in[11];
    const float* db       = (const float*)d_in[12];
    const float* fc1_w    = (const float*)d_in[13];
    const float* fc1_b    = (const float*)d_in[14];
    const float* gate_w   = (const float*)d_in[15];
    const float* gate_b   = (const float*)d_in[16];
    float* out = (float*)d_out;

    kFat<<<FC1_BLOCKS + LSTM_BLOCKS, 320>>>(
        x, fc1_w, fc1_b, bn_gamma, bn_beta, bn_mean, bn_var,
        k1, r1, b1, k2, r2, b2, dw, db);

    kC_gate_combine<<<B_, 320>>>(gate_w, gate_b, out);
}